// round 13
// baseline (speedup 1.0000x reference)
#include <cuda_runtime.h>
#include <cuda_fp16.h>
#include <math.h>
#include <stdint.h>

#define NB 512
#define NTHR 128   // 4-warp CTAs, 4 CTAs/SM -> 4 independent streams
#define NF 64
#define NK 64
#define US 72      // u32 row stride (floats)
#define UHS 72     // u16/w1h row stride (halves) = 9 uint4/row
#define SVS 68     // sv row stride (floats)

typedef unsigned long long ull;

// upper-triangular 8x8 tile enumeration (36 tiles)
__device__ __constant__ unsigned char TI_ARR[36] = {
    0,0,0,0,0,0,0,0,
    1,1,1,1,1,1,1,
    2,2,2,2,2,2,
    3,3,3,3,3,
    4,4,4,4,
    5,5,5,
    6,6,
    7};
__device__ __constant__ unsigned char TJ_ARR[36] = {
    0,1,2,3,4,5,6,7,
    1,2,3,4,5,6,7,
    2,3,4,5,6,7,
    3,4,5,6,7,
    4,5,6,7,
    5,6,7,
    6,7,
    7};

__device__ __forceinline__ uint32_t to_tf32(float f) {
    uint32_t r;
    asm("cvt.rna.tf32.f32 %0, %1;" : "=r"(r) : "f"(f));
    return r;
}
__device__ __forceinline__ uint32_t hmul2(uint32_t a, uint32_t b) {
    uint32_t d;
    asm("mul.rn.f16x2 %0, %1, %2;" : "=r"(d) : "r"(a), "r"(b));
    return d;
}
__device__ __forceinline__ uint32_t packh2(float lo, float hi) {
    uint32_t d;
    asm("cvt.rn.f16x2.f32 %0, %1, %2;" : "=r"(d) : "f"(hi), "f"(lo));
    return d;
}
__device__ __forceinline__ uint32_t packh2_relu(float lo, float hi) {
    uint32_t d;
    asm("cvt.rn.relu.f16x2.f32 %0, %1, %2;" : "=r"(d) : "f"(hi), "f"(lo));
    return d;
}

// D[16x8] += A[16x16](f16) * B[16x8](f16 col-major), f32 accum
__device__ __forceinline__ void mma16(float c[4],
                                      uint32_t a0, uint32_t a1,
                                      uint32_t a2, uint32_t a3,
                                      uint32_t b0, uint32_t b1) {
    asm("mma.sync.aligned.m16n8k16.row.col.f32.f16.f16.f32 "
        "{%0,%1,%2,%3}, {%4,%5,%6,%7}, {%8,%9}, {%0,%1,%2,%3};"
        : "+f"(c[0]), "+f"(c[1]), "+f"(c[2]), "+f"(c[3])
        : "r"(a0), "r"(a1), "r"(a2), "r"(a3), "r"(b0), "r"(b1));
}
// D[16x8] += A[16x8](tf32) * B[8x8](tf32 col-major)  (pass 3)
__device__ __forceinline__ void mma8(float c[4],
                                     uint32_t a0, uint32_t a1,
                                     uint32_t a2, uint32_t a3,
                                     uint32_t b0, uint32_t b1) {
    asm("mma.sync.aligned.m16n8k8.row.col.f32.tf32.tf32.f32 "
        "{%0,%1,%2,%3}, {%4,%5,%6,%7}, {%8,%9}, {%0,%1,%2,%3};"
        : "+f"(c[0]), "+f"(c[1]), "+f"(c[2]), "+f"(c[3])
        : "r"(a0), "r"(a1), "r"(a2), "r"(a3), "r"(b0), "r"(b1));
}

// f32 fragment position (pass 3): k -> 16*(k>>4) + 4*(k&3) + ((k>>2)&3)
__device__ __forceinline__ int posk(int k) {
    return ((k >> 4) << 4) | ((k & 3) << 2) | ((k >> 2) & 3);
}

// dynamic smem (floats)
#define OFF_U32 0                       // 4608 (64*72)
#define OFF_U16 4608                    // 2304 (64*72 halves)
#define OFF_W1H 6912                    // 2304
#define OFF_SV  9216                    // 4352 (64*68)
#define DSM_FLOATS 13568                // 54,272 B

__global__ void __launch_bounds__(NTHR, 4)
afm_kernel(const float* __restrict__ x,
           const float* __restrict__ Ww,  const float* __restrict__ bw,
           const float* __restrict__ cross,
           const float* __restrict__ W1,  const float* __restrict__ b1,
           const float* __restrict__ w2,
           const float* __restrict__ Wd1, const float* __restrict__ bd1,
           const float* __restrict__ Wd2, const float* __restrict__ bd2,
           const float* __restrict__ Wd3, const float* __restrict__ bd3,
           const float* __restrict__ Wo,  const float* __restrict__ bo,
           float* __restrict__ out)
{
    extern __shared__ float dsm[];
    float*   u    = dsm + OFF_U32;
    __half*  u16p = (__half*)(dsm + OFF_U16);
    __half*  w1p  = (__half*)(dsm + OFF_W1H);
    float*   sv   = dsm + OFF_SV;

    __shared__ __align__(16) float xb[NF];
    __shared__ float b1s[NK], w2s[NK];
    __shared__ float redbuf[8];            // [0..4) warp maxes, [4..8) warp sums
    __shared__ float acc4s[4][NK];
    __shared__ float tmpv[NK];
    __shared__ float d1s[32], d2s[24], d3s[16];

    const int b    = blockIdx.x;
    const int tid  = threadIdx.x;
    const int wid  = tid >> 5;      // 0..3
    const int lane = tid & 31;
    const int grp  = lane >> 2;     // 0..7
    const int qc   = lane & 3;      // 0..3

    if (tid < NF) {
        xb[tid]  = x[b * NF + tid];
        b1s[tid] = b1[tid];
        w2s[tid] = w2[tid];
    }
    __syncthreads();

    // ---- staging: u32 (posk), u16/W1h (chunk layout), zero sv ----
    {
        const float4* cr4 = (const float4*)cross;
        const float4* W14 = (const float4*)W1;
        __half2* u16h = (__half2*)u16p;
        __half2* w1h2 = (__half2*)w1p;
        #pragma unroll
        for (int it = 0; it < 8; it++) {
            const int q4 = tid + it * NTHR;
            const int r  = q4 >> 4;
            const int c4 = q4 & 15;
            const float s = xb[r];
            const float4 cc = cr4[q4];
            float4 uu;
            uu.x = s*cc.x; uu.y = s*cc.y; uu.z = s*cc.z; uu.w = s*cc.w;
            // u32: posk layout, row stride 72 floats
            const int kb = c4 << 2;
            const int b32 = r * US + ((kb >> 4) << 4) + ((kb >> 2) & 3);
            u[b32 + 0]  = uu.x;
            u[b32 + 4]  = uu.y;
            u[b32 + 8]  = uu.z;
            u[b32 + 12] = uu.w;
            // fp16 chunk layout (half2 units): r*36 + 16*(c4&1) + 2*(c4>>2) + ((c4>>1)&1)
            const int h2base = (r * UHS + (((c4 & 1) << 1) << 4)
                                + ((c4 >> 2) << 2) + (((c4 >> 1) & 1) << 1)) >> 1;
            u16h[h2base]     = __floats2half2_rn(uu.x, uu.y);
            u16h[h2base + 8] = __floats2half2_rn(uu.z, uu.w);
            const float4 w4 = W14[q4];
            w1h2[h2base]     = __floats2half2_rn(w4.x, w4.y);
            w1h2[h2base + 8] = __floats2half2_rn(w4.z, w4.w);
        }
        // zero sv (pass 1 accumulates into it atomically)
        const float4 z = make_float4(0.f, 0.f, 0.f, 0.f);
        float4* sv4 = (float4*)sv;
        #pragma unroll
        for (int it = 0; it < 9; it++) {
            const int i = tid + it * NTHR;
            if (i < 1088) sv4[i] = z;
        }
    }
    __syncthreads();

    // ---------------- Pass 1: attention scores via fp16 mma.sync -----------
    const int nh = wid & 1;
    const int wp = wid >> 1;        // 0..1

    uint2 Bc[4][4];                 // [nt][k16-step]
    #pragma unroll
    for (int nt = 0; nt < 4; nt++) {
        const uint4* wr4 = (const uint4*)(w1p + ((nh * 4 + nt) * 8 + grp) * UHS);
        const uint4 v0 = wr4[2 * qc];
        const uint4 v1 = wr4[2 * qc + 1];
        Bc[nt][0] = make_uint2(v0.x, v0.y);
        Bc[nt][1] = make_uint2(v0.z, v0.w);
        Bc[nt][2] = make_uint2(v1.x, v1.y);
        Bc[nt][3] = make_uint2(v1.z, v1.w);
    }
    uint32_t w2f[2][2];
    #pragma unroll
    for (int s = 0; s < 2; s++) {
        const int base = nh * 32 + 16 * s;
        w2f[s][0] = packh2(w2s[base + 2 * qc],     w2s[base + 2 * qc + 1]);
        w2f[s][1] = packh2(w2s[base + 8 + 2 * qc], w2s[base + 8 + 2 * qc + 1]);
    }
    float2 b1f[4];
    #pragma unroll
    for (int nt = 0; nt < 4; nt++) {
        b1f[nt].x = b1s[nh * 32 + nt * 8 + 2 * qc];
        b1f[nt].y = b1s[nh * 32 + nt * 8 + 2 * qc + 1];
    }
    float wmax = -3.4e38f;           // max of this warp's partial scores

    for (int p = wp; p < 72; p += 2) {
        const int t  = p >> 1;
        const int h  = p & 1;
        const int ib = TI_ARR[t] * 8 + 4 * h;
        const int jb = TJ_ARR[t] * 8;
        const uint4* uj4 = (const uint4*)(u16p + (jb + grp) * UHS);
        const uint4* ua4 = (const uint4*)(u16p + ib * UHS);  // +9 per row

        float acc0[4][4], acc1[4][4];
        #pragma unroll
        for (int nt = 0; nt < 4; nt++) {
            acc0[nt][0] = b1f[nt].x; acc0[nt][1] = b1f[nt].y;
            acc0[nt][2] = b1f[nt].x; acc0[nt][3] = b1f[nt].y;
            acc1[nt][0] = b1f[nt].x; acc1[nt][1] = b1f[nt].y;
            acc1[nt][2] = b1f[nt].x; acc1[nt][3] = b1f[nt].y;
        }

        #pragma unroll
        for (int c = 0; c < 2; c++) {
            const int o = 2 * qc + c;
            const uint4 uj = uj4[o];
            const uint4 q0 = ua4[o];
            const uint4 q1 = ua4[o + 9];
            const uint4 q2 = ua4[o + 18];
            const uint4 q3 = ua4[o + 27];
            {
                const uint32_t a0 = hmul2(q0.x, uj.x);
                const uint32_t a1 = hmul2(q1.x, uj.x);
                const uint32_t a2 = hmul2(q0.y, uj.y);
                const uint32_t a3 = hmul2(q1.y, uj.y);
                const uint32_t c0 = hmul2(q2.x, uj.x);
                const uint32_t c1 = hmul2(q3.x, uj.x);
                const uint32_t c2 = hmul2(q2.y, uj.y);
                const uint32_t c3 = hmul2(q3.y, uj.y);
                #pragma unroll
                for (int nt = 0; nt < 4; nt++) {
                    mma16(acc0[nt], a0, a1, a2, a3,
                          Bc[nt][2 * c].x, Bc[nt][2 * c].y);
                    mma16(acc1[nt], c0, c1, c2, c3,
                          Bc[nt][2 * c].x, Bc[nt][2 * c].y);
                }
            }
            {
                const uint32_t a0 = hmul2(q0.z, uj.z);
                const uint32_t a1 = hmul2(q1.z, uj.z);
                const uint32_t a2 = hmul2(q0.w, uj.w);
                const uint32_t a3 = hmul2(q1.w, uj.w);
                const uint32_t c0 = hmul2(q2.z, uj.z);
                const uint32_t c1 = hmul2(q3.z, uj.z);
                const uint32_t c2 = hmul2(q2.w, uj.w);
                const uint32_t c3 = hmul2(q3.w, uj.w);
                #pragma unroll
                for (int nt = 0; nt < 4; nt++) {
                    mma16(acc0[nt], a0, a1, a2, a3,
                          Bc[nt][2 * c + 1].x, Bc[nt][2 * c + 1].y);
                    mma16(acc1[nt], c0, c1, c2, c3,
                          Bc[nt][2 * c + 1].x, Bc[nt][2 * c + 1].y);
                }
            }
        }

        // tensor-core epilogue: s = relu(H) . w2, independent MMA pairs
        float sA[4] = {0.f, 0.f, 0.f, 0.f};
        float sB[4] = {0.f, 0.f, 0.f, 0.f};
        mma16(sA,
              packh2_relu(acc0[0][0], acc0[0][1]),
              packh2_relu(acc0[0][2], acc0[0][3]),
              packh2_relu(acc0[1][0], acc0[1][1]),
              packh2_relu(acc0[1][2], acc0[1][3]),
              w2f[0][0], w2f[0][1]);
        mma16(sB,
              packh2_relu(acc0[2][0], acc0[2][1]),
              packh2_relu(acc0[2][2], acc0[2][3]),
              packh2_relu(acc0[3][0], acc0[3][1]),
              packh2_relu(acc0[3][2], acc0[3][3]),
              w2f[1][0], w2f[1][1]);
        float sC[4] = {0.f, 0.f, 0.f, 0.f};
        float sD[4] = {0.f, 0.f, 0.f, 0.f};
        mma16(sC,
              packh2_relu(acc1[0][0], acc1[0][1]),
              packh2_relu(acc1[0][2], acc1[0][3]),
              packh2_relu(acc1[1][0], acc1[1][1]),
              packh2_relu(acc1[1][2], acc1[1][3]),
              w2f[0][0], w2f[0][1]);
        mma16(sD,
              packh2_relu(acc1[2][0], acc1[2][1]),
              packh2_relu(acc1[2][2], acc1[2][3]),
              packh2_relu(acc1[3][0], acc1[3][1]),
              packh2_relu(acc1[3][2], acc1[3][3]),
              w2f[1][0], w2f[1][1]);

        const float r0 = sA[0] + sB[0];
        const float r1 = sA[2] + sB[2];
        const float r2 = sC[0] + sD[0];
        const float r3 = sC[2] + sD[2];
        wmax = fmaxf(wmax, fmaxf(fmaxf(r0, r1), fmaxf(r2, r3)));

        if (qc == 0) {
            const int j = jb + grp;
            atomicAdd(&sv[(ib + 0) * SVS + j], r0);
            atomicAdd(&sv[(ib + 1) * SVS + j], r1);
            atomicAdd(&sv[(ib + 2) * SVS + j], r2);
            atomicAdd(&sv[(ib + 3) * SVS + j], r3);
        }
    }
    #pragma unroll
    for (int d = 16; d; d >>= 1)
        wmax = fmaxf(wmax, __shfl_xor_sync(~0u, wmax, d));
    if (lane == 0) redbuf[wid] = wmax;
    __syncthreads();

    // m = max(0, maxP0 + maxP1) >= true max (valid softmax shift, exact math)
    const float mP0 = fmaxf(redbuf[0], redbuf[2]);
    const float mP1 = fmaxf(redbuf[1], redbuf[3]);
    const float m = fmaxf(0.f, mP0 + mP1);

    // ------------ Pass 2: vectorized masked softmax (float4) -------------
    float le = 0.f;
    #pragma unroll
    for (int it = 0; it < 8; it++) {
        const int lin4 = tid + it * NTHR;     // float4 index, 0..1023
        const int i  = lin4 >> 4;
        const int j0 = (lin4 & 15) << 2;
        const int sidx = i * SVS + j0;
        const float4 sa = *(const float4*)(sv + sidx);
        const float  xi = xb[i];
        const float4 xj = *(const float4*)(xb + j0);
        const bool vi = (xi != 0.f);
        float4 e;
        e.x = (vi && j0 + 0 >= i && xj.x != 0.f) ? __expf(sa.x - m) : 0.f;
        e.y = (vi && j0 + 1 >= i && xj.y != 0.f) ? __expf(sa.y - m) : 0.f;
        e.z = (vi && j0 + 2 >= i && xj.z != 0.f) ? __expf(sa.z - m) : 0.f;
        e.w = (vi && j0 + 3 >= i && xj.w != 0.f) ? __expf(sa.w - m) : 0.f;
        e.x = __uint_as_float(to_tf32(e.x));  // exactly what pass 3's MMA sees
        e.y = __uint_as_float(to_tf32(e.y));
        e.z = __uint_as_float(to_tf32(e.z));
        e.w = __uint_as_float(to_tf32(e.w));
        *(float4*)(sv + sidx) = e;
        le += (e.x + e.y) + (e.z + e.w);
    }
    #pragma unroll
    for (int d = 16; d; d >>= 1) le += __shfl_xor_sync(~0u, le, d);
    if (lane == 0) redbuf[4 + wid] = le;
    __syncthreads();

    // -------- Pass 3: V = E @ U via tf32 mma; tmp[k] = sum_i u[i,k] V[i,k] --
    {
        const int mt = wid;                    // 0..3

        float vacc[8][4];
        #pragma unroll
        for (int cc = 0; cc < 8; cc++)
            #pragma unroll
            for (int q = 0; q < 4; q++) vacc[cc][q] = 0.f;

        int pkb[8];
        #pragma unroll
        for (int cc = 0; cc < 8; cc++)
            pkb[cc] = posk(8 * cc + grp);

        const float* e0 = sv + (16 * mt + grp) * SVS;
        const float* e1 = sv + (16 * mt + grp + 8) * SVS;

        #pragma unroll
        for (int js = 0; js < 8; js++) {
            const int jc = 8 * js + qc;
            const uint32_t a0 = __float_as_uint(e0[jc]);
            const uint32_t a1 = __float_as_uint(e1[jc]);
            const uint32_t a2 = __float_as_uint(e0[jc + 4]);
            const uint32_t a3 = __float_as_uint(e1[jc + 4]);
            const float* uj0 = u + jc * US;
            const float* uj1 = u + (jc + 4) * US;
            #pragma unroll
            for (int cc = 0; cc < 8; cc++) {
                const uint32_t b0 = __float_as_uint(uj0[pkb[cc]]);
                const uint32_t b1v = __float_as_uint(uj1[pkb[cc]]);
                mma8(vacc[cc], a0, a1, a2, a3, b0, b1v);
            }
        }

        float part[16];
        #pragma unroll
        for (int cc = 0; cc < 8; cc++) {
            const int k0 = 8 * cc + 2 * qc;
            const int i0 = 16 * mt + grp;
            const float u00 = u[i0 * US + posk(k0)];
            const float u01 = u[i0 * US + posk(k0 + 1)];
            const float u10 = u[(i0 + 8) * US + posk(k0)];
            const float u11 = u[(i0 + 8) * US + posk(k0 + 1)];
            part[2 * cc]     = fmaf(vacc[cc][0], u00, vacc[cc][2] * u10);
            part[2 * cc + 1] = fmaf(vacc[cc][1], u01, vacc[cc][3] * u11);
        }
        #pragma unroll
        for (int d = 4; d <= 16; d <<= 1)
            #pragma unroll
            for (int q = 0; q < 16; q++)
                part[q] += __shfl_xor_sync(0xffffffffu, part[q], d);

        if (grp == 0) {   // lanes 0..3 (lane == qc)
            #pragma unroll
            for (int cc = 0; cc < 8; cc++) {
                const int k0 = 8 * cc + 2 * qc;
                acc4s[mt][k0]     = part[2 * cc];
                acc4s[mt][k0 + 1] = part[2 * cc + 1];
            }
        }
    }
    __syncthreads();
    if (tid < NK) {
        float denom = __expf(-m);          // seed zeros(1) entry
        #pragma unroll
        for (int w = 0; w < 4; w++) denom += redbuf[4 + w];
        tmpv[tid] = (acc4s[0][tid] + acc4s[1][tid] +
                     acc4s[2][tid] + acc4s[3][tid]) / denom;
    }
    __syncthreads();

    // ---------------- Pass 4: deep MLP on warp 0 (gmem weights) ------------
    if (wid == 0) {
        {
            float a = bd1[lane];
            const float4* w4 = (const float4*)(Wd1 + lane * 64);
            #pragma unroll 4
            for (int j4 = 0; j4 < 16; j4++) {
                const float4 wv = w4[j4];
                a = fmaf(wv.x, tmpv[4 * j4 + 0], a);
                a = fmaf(wv.y, tmpv[4 * j4 + 1], a);
                a = fmaf(wv.z, tmpv[4 * j4 + 2], a);
                a = fmaf(wv.w, tmpv[4 * j4 + 3], a);
            }
            d1s[lane] = fmaxf(a, 0.f);
        }
        __syncwarp();
        if (lane < 21) {
            float a = bd2[lane];
            const float4* w4 = (const float4*)(Wd2 + lane * 32);
            #pragma unroll
            for (int j4 = 0; j4 < 8; j4++) {
                const float4 wv = w4[j4];
                a = fmaf(wv.x, d1s[4 * j4 + 0], a);
                a = fmaf(wv.y, d1s[4 * j4 + 1], a);
                a = fmaf(wv.z, d1s[4 * j4 + 2], a);
                a = fmaf(wv.w, d1s[4 * j4 + 3], a);
            }
            d2s[lane] = fmaxf(a, 0.f);
        }
        __syncwarp();
        if (lane < 16) {
            float a = bd3[lane];
            const float* w = Wd3 + lane * 21;
            #pragma unroll
            for (int j = 0; j < 21; j++) a = fmaf(w[j], d2s[j], a);
            d3s[lane] = fmaxf(a, 0.f);
        }
        __syncwarp();
        if (lane == 0) {
            float o = bo[0];
            #pragma unroll
            for (int j = 0; j < 16; j++) o = fmaf(Wo[j], d3s[j], o);
            float lin = bw[0];
            #pragma unroll 8
            for (int f = 0; f < NF; f++) lin = fmaf(Ww[f], xb[f], lin);
            out[b] = 1.f / (1.f + __expf(-(lin + o)));
        }
    }
}

extern "C" void kernel_launch(void* const* d_in, const int* in_sizes, int n_in,
                              void* d_out, int out_size)
{
    const float* x     = (const float*)d_in[0];
    const float* Ww    = (const float*)d_in[1];
    const float* bw    = (const float*)d_in[2];
    const float* cross = (const float*)d_in[3];
    const float* W1    = (const float*)d_in[4];
    const float* b1    = (const float*)d_in[5];
    const float* w2    = (const float*)d_in[6];
    const float* Wd1   = (const float*)d_in[7];
    const float* bd1   = (const float*)d_in[8];
    const float* Wd2   = (const float*)d_in[9];
    const float* bd2   = (const float*)d_in[10];
    const float* Wd3   = (const float*)d_in[11];
    const float* bd3   = (const float*)d_in[12];
    const float* Wo    = (const float*)d_in[13];
    const float* bo    = (const float*)d_in[14];
    float* out = (float*)d_out;

    const size_t dyn_smem = (size_t)DSM_FLOATS * sizeof(float); // 54,272 B
    cudaFuncSetAttribute(afm_kernel,
                         cudaFuncAttributeMaxDynamicSharedMemorySize,
                         (int)dyn_smem);

    afm_kernel<<<NB, NTHR, dyn_smem>>>(x, Ww, bw, cross, W1, b1, w2,
                                       Wd1, bd1, Wd2, bd2, Wd3, bd3, Wo, bo,
                                       out);
}